// round 1
// baseline (speedup 1.0000x reference)
#include <cuda_runtime.h>
#include <math.h>

#define NB 256   // batch
#define NI 128   // input capsules
#define DD 256   // input feature dim
#define NO 32    // output capsules
#define HH 64    // in_dim == out_dim == 64
#define ITERS 3

// ---- scratch (device globals; no allocation allowed) ----
__device__ float g_u[(size_t)NB * NI * HH];            // squashed primary caps, 8 MB
__device__ float g_ai[NB * NI];                        // ||u||
__device__ float g_votes[(size_t)NB * NO * NI * HH];   // layout [n][o][i][h], 256 MB
__device__ float g_b[(size_t)NB * NI * NO];            // routing logits
__device__ float g_c[(size_t)NB * NI * NO];            // routing coefficients (incl. ai)
__device__ float g_v[(size_t)NB * NO * HH];            // per-iter output caps

// ============================================================
// K1: u[n,i,h] = squash( x[n,i,:] @ Wcap[i] + Bcap[i] ), ai = ||u||
// grid (8 n-tiles, 128 i), 256 threads: (n_sub = t>>6, h = t&63)
// ============================================================
__global__ __launch_bounds__(256) void k_u(const float* __restrict__ x,
                                           const float* __restrict__ Wcap,
                                           const float* __restrict__ Bcap) {
    const int i  = blockIdx.y;
    const int n0 = blockIdx.x * 32;
    const int t  = threadIdx.x;
    const int h  = t & 63;
    const int ns = t >> 6;
    const int lane = t & 31, warp = t >> 5;

    __shared__ float sx[4 * 256];
    __shared__ float spart[8];

    const float bc = Bcap[i * HH + h];
    const float* wp = Wcap + (size_t)i * DD * HH + h;

    for (int ch = 0; ch < 8; ++ch) {
        const int nb = n0 + ch * 4;
        __syncthreads();
        #pragma unroll
        for (int idx = t; idx < 1024; idx += 256)
            sx[idx] = x[((size_t)(nb + (idx >> 8)) * NI + i) * DD + (idx & 255)];
        __syncthreads();

        float acc = bc;
        const float* xp = sx + ns * 256;
        #pragma unroll 8
        for (int d = 0; d < DD; ++d)
            acc += xp[d] * wp[(size_t)d * HH];

        // squash over h (64 values = 2 warps per n_sub group)
        float sq = acc * acc;
        #pragma unroll
        for (int off = 16; off; off >>= 1) sq += __shfl_xor_sync(0xffffffffu, sq, off);
        if (lane == 0) spart[warp] = sq;
        __syncthreads();
        const float n2  = spart[ns * 2] + spart[ns * 2 + 1];
        const float nrm = sqrtf(n2);
        const float f   = (n2 / (n2 + 1.0f)) / (nrm + 1e-8f);
        const int n = nb + ns;
        g_u[((size_t)n * NI + i) * HH + h] = acc * f;
        if (h == 0) g_ai[n * NI + i] = f * nrm;
    }
}

// ============================================================
// K2: votes[n,o,i,h] = mask[n,i] * ( u[n,i,:] @ Wv[i,o] + Bv[i,o,h] )
// grid (32 o, 128 i), 256 threads. W tile (64x64) cached in registers
// (64 regs/thread), u tiles staged through smem broadcast.
// ============================================================
__global__ __launch_bounds__(256) void k_votes(const float* __restrict__ Wv,
                                               const float* __restrict__ Bv,
                                               const float* __restrict__ mask) {
    const int o = blockIdx.x, i = blockIdx.y;
    const int t = threadIdx.x;
    const int h = t & 63, g = t >> 6;

    __shared__ float su[16 * 64];

    float w[64];
    const float* wsrc = Wv + ((size_t)(i * NO + o)) * 64 * 64 + h;
    #pragma unroll
    for (int d = 0; d < 64; ++d) w[d] = wsrc[(size_t)d * 64];
    const float bv = Bv[(i * NO + o) * 64 + h];

    // votes index: n*(NO*NI*HH) + o*(NI*HH) + i*HH + h
    float* vdst = g_votes + ((size_t)o * NI + i) * HH + h;
    const size_t nstride = (size_t)NO * NI * HH;

    for (int nb = 0; nb < NB; nb += 16) {
        __syncthreads();
        #pragma unroll
        for (int idx = t; idx < 1024; idx += 256)
            su[idx] = g_u[((size_t)(nb + (idx >> 6)) * NI + i) * HH + (idx & 63)];
        __syncthreads();

        float a0 = bv, a1 = bv, a2 = bv, a3 = bv;
        const float* u0 = su + (g * 4 + 0) * 64;
        const float* u1 = su + (g * 4 + 1) * 64;
        const float* u2 = su + (g * 4 + 2) * 64;
        const float* u3 = su + (g * 4 + 3) * 64;
        #pragma unroll
        for (int d = 0; d < 64; ++d) {
            const float wv = w[d];
            a0 += u0[d] * wv;
            a1 += u1[d] * wv;
            a2 += u2[d] * wv;
            a3 += u3[d] * wv;
        }
        const int n = nb + g * 4;
        a0 *= mask[(n + 0) * NI + i];
        a1 *= mask[(n + 1) * NI + i];
        a2 *= mask[(n + 2) * NI + i];
        a3 *= mask[(n + 3) * NI + i];
        vdst[(size_t)(n + 0) * nstride] = a0;
        vdst[(size_t)(n + 1) * nstride] = a1;
        vdst[(size_t)(n + 2) * nstride] = a2;
        vdst[(size_t)(n + 3) * nstride] = a3;
    }
}

// ============================================================
// K3: s[n,o,:] = sum_i c[n,i,o] * votes[n,o,i,:]; v = squash(s)
// First iter: c = ai/33 (b==0 -> uniform softmax over 33 entries).
// grid (32 o, 256 n), 256 threads: (g = t>>6 strides i, h = t&63)
// ============================================================
__global__ __launch_bounds__(256) void k_sum(int first, int last, float* __restrict__ out) {
    const int o = blockIdx.x, n = blockIdx.y;
    const int t = threadIdx.x;
    const int h = t & 63, g = t >> 6;
    const int lane = t & 31, warp = t >> 5;

    float acc = 0.0f;
    const float* vp = g_votes + ((size_t)n * NO + o) * NI * HH + h;
    if (first) {
        const float* aip = g_ai + n * NI;
        #pragma unroll 4
        for (int i = g; i < NI; i += 4)
            acc += (aip[i] * (1.0f / 33.0f)) * vp[(size_t)i * HH];
    } else {
        const float* cp = g_c + ((size_t)n * NI) * NO + o;
        #pragma unroll 4
        for (int i = g; i < NI; i += 4)
            acc += cp[(size_t)i * NO] * vp[(size_t)i * HH];
    }

    __shared__ float sred[4][64];
    __shared__ float spart[8];
    sred[g][h] = acc;
    __syncthreads();
    const float s = sred[0][h] + sred[1][h] + sred[2][h] + sred[3][h];

    float sq = s * s;
    #pragma unroll
    for (int off = 16; off; off >>= 1) sq += __shfl_xor_sync(0xffffffffu, sq, off);
    if (lane == 0) spart[warp] = sq;
    __syncthreads();
    const float n2  = spart[0] + spart[1];
    const float nrm = sqrtf(n2);
    const float f   = (n2 / (n2 + 1.0f)) / (nrm + 1e-8f);

    float* dst = last ? out : g_v;
    if (t < 64) dst[((size_t)n * NO + o) * HH + h] = s * f;
}

// ============================================================
// K4: agree[n,i,o] = votes[n,o,i,:] . v[n,o,:];  b += agree;
//     c[n,i,o] = ai[n,i] * softmax_o([0, b])[o+1]   (leaky softmax, leak=0)
// grid (128 i, 256 n), 256 threads (8 warps; warp w handles o = 4k+... )
// ============================================================
__global__ __launch_bounds__(256) void k_agree(int first) {
    const int i = blockIdx.x, n = blockIdx.y;
    const int t = threadIdx.x;
    const int lane = t & 31, warp = t >> 5;

    __shared__ float sv[NO * HH];     // 8 KB
    __shared__ float sagree[NO];

    #pragma unroll
    for (int idx = t; idx < NO * HH; idx += 256)
        sv[idx] = g_v[(size_t)n * NO * HH + idx];
    __syncthreads();

    const float* base = g_votes + (size_t)n * NO * NI * HH + (size_t)i * HH;
    #pragma unroll
    for (int k = 0; k < 4; ++k) {
        const int o = k * 8 + warp;
        const float2 vt = reinterpret_cast<const float2*>(base + (size_t)o * NI * HH)[lane];
        const float2 vv = reinterpret_cast<const float2*>(sv + o * HH)[lane];
        float p = vt.x * vv.x + vt.y * vv.y;
        #pragma unroll
        for (int off = 16; off; off >>= 1) p += __shfl_xor_sync(0xffffffffu, p, off);
        if (lane == 0) sagree[o] = p;
    }
    __syncthreads();

    if (t < 32) {
        const int o = t;
        const size_t bidx = ((size_t)n * NI + i) * NO + o;
        float b = first ? 0.0f : g_b[bidx];
        b += sagree[o];
        if (first) g_b[bidx] = b;   // only iter-1's b is ever re-read

        // stable softmax over [leak=0, b_0..b_31]
        float m = b;
        #pragma unroll
        for (int off = 16; off; off >>= 1) m = fmaxf(m, __shfl_xor_sync(0xffffffffu, m, off));
        m = fmaxf(m, 0.0f);
        const float e = expf(b - m);
        float sum = e;
        #pragma unroll
        for (int off = 16; off; off >>= 1) sum += __shfl_xor_sync(0xffffffffu, sum, off);
        sum += expf(-m);   // leak term
        const float ai = g_ai[n * NI + i];
        g_c[bidx] = ai * e / sum;
    }
}

// ============================================================
extern "C" void kernel_launch(void* const* d_in, const int* in_sizes, int n_in,
                              void* d_out, int out_size) {
    const float* x    = (const float*)d_in[0];
    const float* mask = (const float*)d_in[1];
    const float* Wcap = (const float*)d_in[2];
    const float* Bcap = (const float*)d_in[3];
    const float* Wv   = (const float*)d_in[4];
    const float* Bv   = (const float*)d_in[5];
    float* out = (float*)d_out;

    k_u    <<<dim3(8, 128),  256>>>(x, Wcap, Bcap);
    k_votes<<<dim3(32, 128), 256>>>(Wv, Bv, mask);

    // iter 1
    k_sum  <<<dim3(32, 256), 256>>>(1, 0, out);
    k_agree<<<dim3(128, 256), 256>>>(1);
    // iter 2
    k_sum  <<<dim3(32, 256), 256>>>(0, 0, out);
    k_agree<<<dim3(128, 256), 256>>>(0);
    // iter 3 (final -> d_out)
    k_sum  <<<dim3(32, 256), 256>>>(0, 1, out);
}

// round 3
// speedup vs baseline: 1.9065x; 1.9065x over previous
#include <cuda_runtime.h>
#include <cuda_fp16.h>
#include <stdint.h>
#include <math.h>

#define NB 256   // batch
#define NI 128   // input capsules
#define DD 256   // input feature dim
#define NO 32    // output capsules
#define HH 64    // in_dim == out_dim

// ---- scratch (device globals; no allocation allowed) ----
__device__ __half g_votes[(size_t)NB * NI * NO * HH];  // [n][i][o][h] fp16, 134 MB
__device__ __half g_uh[(size_t)NB * NI * HH];          // squashed u fp16, 4 MB
__device__ float  g_ai[NB * NI];                       // ||u||
__device__ float  g_b[(size_t)NB * NI * NO];           // routing logits (iter-2 b)
__device__ float  g_v[(size_t)NB * NO * HH];           // per-iter output caps
__device__ float  g_spart[2ull * NB * NO * HH];        // partial sums (2 i-halves)

__device__ __forceinline__ uint32_t smem_u32(const void* p) {
    uint32_t a;
    asm("{ .reg .u64 t; cvta.to.shared.u64 t, %1; cvt.u32.u64 %0, t; }" : "=r"(a) : "l"(p));
    return a;
}

// ============================================================
// K1: u[n,i,h] = squash( x[n,i,:] @ Wcap[i] + Bcap[i] ) -> fp16, ai = ||u||
// ============================================================
__global__ __launch_bounds__(256) void k_u(const float* __restrict__ x,
                                           const float* __restrict__ Wcap,
                                           const float* __restrict__ Bcap) {
    const int i  = blockIdx.y;
    const int n0 = blockIdx.x * 32;
    const int t  = threadIdx.x;
    const int h  = t & 63;
    const int ns = t >> 6;
    const int lane = t & 31, warp = t >> 5;

    __shared__ float sx[4 * 256];
    __shared__ float spart[8];

    const float bc = Bcap[i * HH + h];
    const float* wp = Wcap + (size_t)i * DD * HH + h;

    for (int ch = 0; ch < 8; ++ch) {
        const int nb = n0 + ch * 4;
        __syncthreads();
        #pragma unroll
        for (int idx = t; idx < 1024; idx += 256)
            sx[idx] = x[((size_t)(nb + (idx >> 8)) * NI + i) * DD + (idx & 255)];
        __syncthreads();

        float acc = bc;
        const float* xp = sx + ns * 256;
        #pragma unroll 8
        for (int d = 0; d < DD; ++d)
            acc += xp[d] * wp[(size_t)d * HH];

        float sq = acc * acc;
        #pragma unroll
        for (int off = 16; off; off >>= 1) sq += __shfl_xor_sync(0xffffffffu, sq, off);
        if (lane == 0) spart[warp] = sq;
        __syncthreads();
        const float n2  = spart[ns * 2] + spart[ns * 2 + 1];
        const float nrm = sqrtf(n2);
        const float f   = (n2 / (n2 + 1.0f)) / (nrm + 1e-8f);
        const int n = nb + ns;
        g_uh[((size_t)n * NI + i) * HH + h] = __float2half(acc * f);
        if (h == 0) g_ai[n * NI + i] = f * nrm;
    }
}

// ============================================================
// K2 (HMMA): votes[n,i,o,h] = fp16( mask * (u[:,i] @ Wv[i,o] + Bv) )
// block = (o, i), 128 threads / 4 warps. M=256 (n), N=64 (h), K=64 (d).
// A = u[:,i,:] fp16 smem (XOR-swizzled 16B chunks), B = Wv[i,o] fp32->fp16.
// Warp w computes rows 64w..64w+63 via mma.m16n8k16 (4 mt x 8 nt x 4 k).
// ============================================================
__global__ __launch_bounds__(128) void k_votes(const float* __restrict__ Wv,
                                               const float* __restrict__ Bv,
                                               const float* __restrict__ mask) {
    __shared__ __align__(16) unsigned char sm[41216];
    const int o = blockIdx.x, i = blockIdx.y;
    const int t = threadIdx.x, wid = t >> 5, lane = t & 31;
    __half* sA = reinterpret_cast<__half*>(sm);           // 256 x 64 (32 KB)
    __half* sB = reinterpret_cast<__half*>(sm + 32768);   // 64 x 64  (8 KB)
    float*  sbv = reinterpret_cast<float*>(sm + 40960);   // bias (256 B)

    // ---- load A: u[:, i, :] as 16B chunks, chunk ^= (row & 7)
    const uint4* usrc = reinterpret_cast<const uint4*>(g_uh) + (size_t)i * 8;
    #pragma unroll
    for (int idx = t; idx < 2048; idx += 128) {
        const int n = idx >> 3, c = idx & 7;
        uint4 v = usrc[(size_t)n * (NI * 8) + c];
        reinterpret_cast<uint4*>(sA)[n * 8 + (c ^ (n & 7))] = v;
    }
    // ---- load B: Wv[i,o][d][h] fp32 -> fp16, same chunk swizzle per row d
    const float2* wsrc = reinterpret_cast<const float2*>(Wv + ((size_t)(i * NO + o) << 12));
    #pragma unroll
    for (int idx = t; idx < 2048; idx += 128) {
        const int d = idx >> 5, hp = idx & 31;     // hp = half2 index within row
        const float2 f = wsrc[idx];
        const __half2 hv = __floats2half2_rn(f.x, f.y);
        const int c = hp >> 2, w_ = hp & 3;
        reinterpret_cast<__half2*>(sB)[d * 32 + ((c ^ (d & 7)) << 2) + w_] = hv;
    }
    if (t < 64) sbv[t] = Bv[(i * NO + o) * HH + t];
    __syncthreads();

    float acc[4][8][4];
    #pragma unroll
    for (int mt = 0; mt < 4; ++mt)
        #pragma unroll
        for (int nt = 0; nt < 8; ++nt) {
            acc[mt][nt][0] = 0.f; acc[mt][nt][1] = 0.f;
            acc[mt][nt][2] = 0.f; acc[mt][nt][3] = 0.f;
        }

    const uint32_t sA32 = smem_u32(sA);
    const uint32_t sB32 = smem_u32(sB);

    #pragma unroll
    for (int k = 0; k < 4; ++k) {
        uint32_t a[4][4];
        #pragma unroll
        for (int mt = 0; mt < 4; ++mt) {
            const int row = wid * 64 + mt * 16 + (lane & 15);
            const int ch  = (k * 2 + (lane >> 4)) ^ (row & 7);
            const uint32_t addr = sA32 + row * 128 + ch * 16;
            asm volatile("ldmatrix.sync.aligned.m8n8.x4.shared.b16 {%0,%1,%2,%3}, [%4];"
                : "=r"(a[mt][0]), "=r"(a[mt][1]), "=r"(a[mt][2]), "=r"(a[mt][3]) : "r"(addr));
        }
        uint32_t b[8][2];
        #pragma unroll
        for (int nt = 0; nt < 8; ++nt) {
            const int d  = k * 16 + (lane & 15);   // threads 0-15 supply addresses
            const int ch = nt ^ (d & 7);
            const uint32_t addr = sB32 + d * 128 + ch * 16;
            asm volatile("ldmatrix.sync.aligned.m8n8.x2.trans.shared.b16 {%0,%1}, [%2];"
                : "=r"(b[nt][0]), "=r"(b[nt][1]) : "r"(addr));
        }
        #pragma unroll
        for (int mt = 0; mt < 4; ++mt)
            #pragma unroll
            for (int nt = 0; nt < 8; ++nt)
                asm volatile("mma.sync.aligned.m16n8k16.row.col.f32.f16.f16.f32 "
                    "{%0,%1,%2,%3}, {%4,%5,%6,%7}, {%8,%9}, {%0,%1,%2,%3};"
                    : "+f"(acc[mt][nt][0]), "+f"(acc[mt][nt][1]),
                      "+f"(acc[mt][nt][2]), "+f"(acc[mt][nt][3])
                    : "r"(a[mt][0]), "r"(a[mt][1]), "r"(a[mt][2]), "r"(a[mt][3]),
                      "r"(b[nt][0]), "r"(b[nt][1]));
    }
    __syncthreads();   // everyone done reading sA/sB

    // ---- stage (bias added), row stride 72 halfs -> conflict-free
    __half2* stg = reinterpret_cast<__half2*>(sm);
    #pragma unroll
    for (int mt = 0; mt < 4; ++mt) {
        const int r0 = wid * 64 + mt * 16 + (lane >> 2);
        #pragma unroll
        for (int nt = 0; nt < 8; ++nt) {
            const int h = nt * 8 + (lane & 3) * 2;
            const float b0 = sbv[h], b1 = sbv[h + 1];
            stg[(r0 * 72 + h) >> 1] =
                __floats2half2_rn(acc[mt][nt][0] + b0, acc[mt][nt][1] + b1);
            stg[((r0 + 8) * 72 + h) >> 1] =
                __floats2half2_rn(acc[mt][nt][2] + b0, acc[mt][nt][3] + b1);
        }
    }
    __syncthreads();

    // ---- coalesced fp16 stores with mask applied
    #pragma unroll
    for (int p = 0; p < 16; ++p) {
        const int n = p * 16 + (t >> 3), c = t & 7;
        const __half2 mk2 = __float2half2_rn(mask[n * NI + i]);
        uint4 v = *reinterpret_cast<const uint4*>(sm + n * 144 + c * 16);
        __half2* vh = reinterpret_cast<__half2*>(&v);
        vh[0] = __hmul2(vh[0], mk2); vh[1] = __hmul2(vh[1], mk2);
        vh[2] = __hmul2(vh[2], mk2); vh[3] = __hmul2(vh[3], mk2);
        *reinterpret_cast<uint4*>(g_votes + ((size_t)(n * NI + i) * NO + o) * HH + c * 8) = v;
    }
}

// ============================================================
// K3 (fused routing pass): one streaming read of votes per iteration.
// block = (ihalf, n): per i: agree (iters 2,3) -> b -> softmax -> c,
// accumulate s += c * votes, write partial s.
// ============================================================
__global__ __launch_bounds__(256) void k_route(int iter) {
    const int ih = blockIdx.x, n = blockIdx.y;
    const int t = threadIdx.x, o = t >> 3, hg = t & 7;
    __shared__ __align__(16) float sv[NO * HH];
    __shared__ float sai[64], sb2[NO], sc[NO];

    if (iter > 1) {
        #pragma unroll
        for (int idx = t; idx < NO * HH; idx += 256) sv[idx] = g_v[(size_t)n * NO * HH + idx];
    }
    if (t < 64) sai[t] = g_ai[n * NI + ih * 64 + t];
    __syncthreads();

    float sr[8] = {0, 0, 0, 0, 0, 0, 0, 0};
    const uint4* vbase = reinterpret_cast<const uint4*>(
        g_votes + ((size_t)(n * NI + ih * 64)) * NO * HH);

    uint4 raw = vbase[t];
    for (int ii = 0; ii < 64; ++ii) {
        const uint4 cur = raw;
        if (ii < 63) raw = vbase[(size_t)(ii + 1) * 256 + t];

        const float2 f0 = __half22float2(*reinterpret_cast<const __half2*>(&cur.x));
        const float2 f1 = __half22float2(*reinterpret_cast<const __half2*>(&cur.y));
        const float2 f2 = __half22float2(*reinterpret_cast<const __half2*>(&cur.z));
        const float2 f3 = __half22float2(*reinterpret_cast<const __half2*>(&cur.w));

        float c;
        if (iter == 1) {
            c = sai[ii] * (1.0f / 33.0f);
        } else {
            const float4 va = *reinterpret_cast<const float4*>(sv + o * HH + hg * 8);
            const float4 vb = *reinterpret_cast<const float4*>(sv + o * HH + hg * 8 + 4);
            float p = f0.x * va.x + f0.y * va.y + f1.x * va.z + f1.y * va.w
                    + f2.x * vb.x + f2.y * vb.y + f3.x * vb.z + f3.y * vb.w;
            p += __shfl_xor_sync(0xffffffffu, p, 1);
            p += __shfl_xor_sync(0xffffffffu, p, 2);
            p += __shfl_xor_sync(0xffffffffu, p, 4);
            if (hg == 0) {
                const size_t bidx = ((size_t)(n * NI + ih * 64 + ii)) * NO + o;
                float b = p + (iter == 2 ? 0.0f : g_b[bidx]);
                if (iter == 2) g_b[bidx] = b;
                sb2[o] = b;
            }
            __syncthreads();
            if (t < 32) {
                const float b = sb2[t];
                float m = b;
                #pragma unroll
                for (int off = 16; off; off >>= 1) m = fmaxf(m, __shfl_xor_sync(0xffffffffu, m, off));
                m = fmaxf(m, 0.0f);
                const float e = __expf(b - m);
                float s = e;
                #pragma unroll
                for (int off = 16; off; off >>= 1) s += __shfl_xor_sync(0xffffffffu, s, off);
                s += __expf(-m);
                sc[t] = sai[ii] * e / s;
            }
            __syncthreads();
            c = sc[o];
        }
        sr[0] += c * f0.x; sr[1] += c * f0.y; sr[2] += c * f1.x; sr[3] += c * f1.y;
        sr[4] += c * f2.x; sr[5] += c * f2.y; sr[6] += c * f3.x; sr[7] += c * f3.y;
    }

    float* dst = g_spart + ((size_t)(ih * NB + n) * NO + o) * HH + hg * 8;
    *reinterpret_cast<float4*>(dst)     = make_float4(sr[0], sr[1], sr[2], sr[3]);
    *reinterpret_cast<float4*>(dst + 4) = make_float4(sr[4], sr[5], sr[6], sr[7]);
}

// ============================================================
// K4: combine 2 partials, squash over h, write v (or final out).
// ============================================================
__global__ __launch_bounds__(256) void k_fin(int last, float* __restrict__ out) {
    const int n = blockIdx.x;
    const int t = threadIdx.x, o = t >> 3, hg = t & 7;
    const size_t base = ((size_t)n * NO + o) * HH + hg * 8;
    const size_t half2off = (size_t)NB * NO * HH;

    const float4 a0 = *reinterpret_cast<const float4*>(g_spart + base);
    const float4 a1 = *reinterpret_cast<const float4*>(g_spart + base + 4);
    const float4 b0 = *reinterpret_cast<const float4*>(g_spart + half2off + base);
    const float4 b1 = *reinterpret_cast<const float4*>(g_spart + half2off + base + 4);

    float s[8] = {a0.x + b0.x, a0.y + b0.y, a0.z + b0.z, a0.w + b0.w,
                  a1.x + b1.x, a1.y + b1.y, a1.z + b1.z, a1.w + b1.w};
    float q = 0.0f;
    #pragma unroll
    for (int j = 0; j < 8; ++j) q += s[j] * s[j];
    q += __shfl_xor_sync(0xffffffffu, q, 1);
    q += __shfl_xor_sync(0xffffffffu, q, 2);
    q += __shfl_xor_sync(0xffffffffu, q, 4);
    const float nrm = sqrtf(q);
    const float f = (q / (q + 1.0f)) / (nrm + 1e-8f);

    float* dst = (last ? out : g_v) + ((size_t)n * NO + o) * HH + hg * 8;
    #pragma unroll
    for (int j = 0; j < 8; ++j) dst[j] = s[j] * f;
}

// ============================================================
extern "C" void kernel_launch(void* const* d_in, const int* in_sizes, int n_in,
                              void* d_out, int out_size) {
    const float* x    = (const float*)d_in[0];
    const float* mask = (const float*)d_in[1];
    const float* Wcap = (const float*)d_in[2];
    const float* Bcap = (const float*)d_in[3];
    const float* Wv   = (const float*)d_in[4];
    const float* Bv   = (const float*)d_in[5];
    float* out = (float*)d_out;

    k_u    <<<dim3(8, 128),  256>>>(x, Wcap, Bcap);
    k_votes<<<dim3(NO, NI),  128>>>(Wv, Bv, mask);

    k_route<<<dim3(2, NB), 256>>>(1);
    k_fin  <<<NB, 256>>>(0, out);
    k_route<<<dim3(2, NB), 256>>>(2);
    k_fin  <<<NB, 256>>>(0, out);
    k_route<<<dim3(2, NB), 256>>>(3);
    k_fin  <<<NB, 256>>>(1, out);
}